// round 14
// baseline (speedup 1.0000x reference)
#include <cuda_runtime.h>
#include <cuda_bf16.h>
#include <math.h>
#include <stdint.h>

#define NN 200000
#define NE 800000
#define NG 4096
#define F_IN 64
#define HS 768              // concat stride: 128+128+256+256
#define NBUCK 6
#define SLOT_N (NN + NBUCK*128)  // 200768, multiple of 128
#define NTILES (SLOT_N/128)      // 1569
#define SCAN_B 512
#define SCAN_NBLK ((NN + SCAN_B - 1)/SCAN_B)  // 391
#define NDT 24                   // direct logit-partial tiles (768/32)
#define NPT 8                    // pool logit-partial tiles (256/32)

// weight buffer layout: per layer, [bucket][n][k'] with k' = [Wl rows | Wr rows]
#define WOFF0 0
#define WOFF1 (6*128*128)
#define WOFF2 (WOFF1 + 6*256*128)
#define WOFF3 (WOFF2 + 6*256*256)
#define WTOT  (WOFF3 + 6*512*256)

// ---------------- scratch (static device memory; no allocation) ----------------
__device__ float g_hs[(size_t)NN * HS];
__device__ float g_msg[(size_t)NN * 256];
__device__ float g_part[(size_t)NN * NDT * 2];   // per-node direct logit partials
__device__ float g_ppart[(size_t)NN * NPT * 2];  // per-node pool-branch partials
__device__ float g_pl[NG * 2];                   // per-graph pooled logit pair
__device__ __nv_bfloat16 g_wt_hi[WTOT];
__device__ __nv_bfloat16 g_wt_lo[WTOT];
__device__ int   g_rawdeg[NN];
__device__ int   g_deg[NN];
__device__ int   g_rowptr[NN + 1];
__device__ int   g_col[NE];
__device__ int   g_fill[NN];
__device__ int   g_order[SLOT_N];
__device__ int   g_cnt[NBUCK];
__device__ int   g_bfill[NBUCK];
__device__ int   g_pstart[NBUCK + 1];
__device__ int   g_scanpart[SCAN_NBLK];
__device__ int   g_gstart[NG + 1];

// ---------------- helpers ----------------
__device__ __forceinline__ uint32_t smem_u32(const void* p) {
    uint32_t a;
    asm("{ .reg .u64 t; cvta.to.shared.u64 t, %1; cvt.u32.u64 %0, t; }" : "=r"(a) : "l"(p));
    return a;
}
__device__ __forceinline__ void ldm_x4(uint32_t* r, uint32_t addr) {
    asm volatile("ldmatrix.sync.aligned.m8n8.x4.shared.b16 {%0,%1,%2,%3}, [%4];"
                 : "=r"(r[0]), "=r"(r[1]), "=r"(r[2]), "=r"(r[3]) : "r"(addr));
}
__device__ __forceinline__ void mma_bf16(float* d, const uint32_t* a, const uint32_t* b) {
    asm volatile(
        "mma.sync.aligned.m16n8k16.row.col.f32.bf16.bf16.f32 "
        "{%0,%1,%2,%3}, {%4,%5,%6,%7}, {%8,%9}, {%0,%1,%2,%3};"
        : "+f"(d[0]), "+f"(d[1]), "+f"(d[2]), "+f"(d[3])
        : "r"(a[0]), "r"(a[1]), "r"(a[2]), "r"(a[3]), "r"(b[0]), "r"(b[1]));
}
__device__ __forceinline__ uint32_t pk(__nv_bfloat16 a, __nv_bfloat16 b) {
    return (uint32_t)__bfloat16_as_ushort(a) | ((uint32_t)__bfloat16_as_ushort(b) << 16);
}
// convert 8 fp32 -> 8 bf16 hi + 8 bf16 lo (one uint4 each)
__device__ __forceinline__ void cvt8(float4 a, float4 b, uint4* hi, uint4* lo) {
    __nv_bfloat16 h0 = __float2bfloat16(a.x), h1 = __float2bfloat16(a.y);
    __nv_bfloat16 h2 = __float2bfloat16(a.z), h3 = __float2bfloat16(a.w);
    __nv_bfloat16 h4 = __float2bfloat16(b.x), h5 = __float2bfloat16(b.y);
    __nv_bfloat16 h6 = __float2bfloat16(b.z), h7 = __float2bfloat16(b.w);
    hi->x = pk(h0, h1); hi->y = pk(h2, h3); hi->z = pk(h4, h5); hi->w = pk(h6, h7);
    __nv_bfloat16 l0 = __float2bfloat16(a.x - __bfloat162float(h0));
    __nv_bfloat16 l1 = __float2bfloat16(a.y - __bfloat162float(h1));
    __nv_bfloat16 l2 = __float2bfloat16(a.z - __bfloat162float(h2));
    __nv_bfloat16 l3 = __float2bfloat16(a.w - __bfloat162float(h3));
    __nv_bfloat16 l4 = __float2bfloat16(b.x - __bfloat162float(h4));
    __nv_bfloat16 l5 = __float2bfloat16(b.y - __bfloat162float(h5));
    __nv_bfloat16 l6 = __float2bfloat16(b.z - __bfloat162float(h6));
    __nv_bfloat16 l7 = __float2bfloat16(b.w - __bfloat162float(h7));
    lo->x = pk(l0, l1); lo->y = pk(l2, l3); lo->z = pk(l4, l5); lo->w = pk(l6, l7);
}

// ---------------- fused init ----------------
__global__ void k_init() {
    int i = blockIdx.x * blockDim.x + threadIdx.x;
    if (i < NN) g_rawdeg[i] = 0;
    if (i < SLOT_N) g_order[i] = -1;
    if (i < NBUCK) { g_cnt[i] = 0; g_bfill[i] = 0; }
}
__global__ void k_count_deg(const int* __restrict__ dst) {
    int e = blockIdx.x * blockDim.x + threadIdx.x;
    if (e < NE) atomicAdd(&g_rawdeg[dst[e]], 1);
}

// ---------------- scan ----------------
__global__ void k_scan_partial() {
    __shared__ int s[SCAN_B];
    int tid = threadIdx.x;
    int i = blockIdx.x * SCAN_B + tid;
    s[tid] = (i < NN) ? g_rawdeg[i] : 0;
    __syncthreads();
    for (int off = SCAN_B / 2; off > 0; off >>= 1) {
        if (tid < off) s[tid] += s[tid + off];
        __syncthreads();
    }
    if (tid == 0) g_scanpart[blockIdx.x] = s[0];
}
__global__ void k_scan_excl_partials() {   // parallel 512-thread exclusive scan
    __shared__ int s[512];
    int t = threadIdx.x;
    int v = (t < SCAN_NBLK) ? g_scanpart[t] : 0;
    s[t] = v;
    __syncthreads();
    for (int off = 1; off < 512; off <<= 1) {
        int u = (t >= off) ? s[t - off] : 0;
        __syncthreads();
        s[t] += u;
        __syncthreads();
    }
    if (t < SCAN_NBLK) g_scanpart[t] = s[t] - v;
}
__global__ void k_scan_write() {
    __shared__ int s[SCAN_B];
    int tid = threadIdx.x;
    int i = blockIdx.x * SCAN_B + tid;
    int v = (i < NN) ? g_rawdeg[i] : 0;
    s[tid] = v;
    __syncthreads();
    for (int off = 1; off < SCAN_B; off <<= 1) {
        int t = (tid >= off) ? s[tid - off] : 0;
        __syncthreads();
        s[tid] += t;
        __syncthreads();
    }
    int excl = s[tid] - v + g_scanpart[blockIdx.x];
    if (i < NN) g_rowptr[i] = excl;
    if (i == NN - 1) g_rowptr[NN] = excl + v;
}

// ---------------- degree bucket / partition / CSR ----------------
__global__ void k_clamp_count() {
    int i = blockIdx.x * blockDim.x + threadIdx.x;
    if (i >= NN) return;
    int d = g_rawdeg[i]; if (d > 5) d = 5;
    g_deg[i] = d;
    g_fill[i] = 0;
    atomicAdd(&g_cnt[d], 1);
}
__global__ void k_pstart() {
    if (threadIdx.x == 0) {
        int off = 0;
        for (int b = 0; b < NBUCK; b++) { g_pstart[b] = off; off += (g_cnt[b] + 127) & ~127; }
        g_pstart[NBUCK] = off;
    }
}
__global__ void k_scatter_order() {
    int i = blockIdx.x * blockDim.x + threadIdx.x;
    if (i >= NN) return;
    int b = g_deg[i];
    int pos = atomicAdd(&g_bfill[b], 1);
    g_order[g_pstart[b] + pos] = i;
}
__global__ void k_csr_fill(const int* __restrict__ src, const int* __restrict__ dst) {
    int e = blockIdx.x * blockDim.x + threadIdx.x;
    if (e >= NE) return;
    int d = dst[e];
    int pos = atomicAdd(&g_fill[d], 1);
    g_col[g_rowptr[d] + pos] = src[e];
}
__global__ void k_csr_sort() {
    int i = blockIdx.x * blockDim.x + threadIdx.x;
    if (i >= NN) return;
    int a = g_rowptr[i], b = g_rowptr[i + 1];
    for (int j = a + 1; j < b; j++) {
        int v = g_col[j]; int k = j - 1;
        while (k >= a && g_col[k] > v) { g_col[k + 1] = g_col[k]; k--; }
        g_col[k + 1] = v;
    }
}
__global__ void k_gstart(const int* __restrict__ batch) {
    int i = blockIdx.x * blockDim.x + threadIdx.x;
    if (i >= NN) return;
    int b = batch[i];
    int p = (i == 0) ? -1 : batch[i - 1];
    for (int g = p + 1; g <= b; g++) g_gstart[g] = i;
    if (i == NN - 1) { for (int g = b + 1; g <= NG; g++) g_gstart[g] = NN; }
}

// ---------------- weight prep: transpose + bf16 hi/lo split ----------------
__global__ void k_prep_w(const float* __restrict__ Wl, const float* __restrict__ Wr,
                         int c_in, int c_out, size_t base) {
    int idx = blockIdx.x * blockDim.x + threadIdx.x;
    int Kp = 2 * c_in;
    int per = Kp * c_out;
    int total = NBUCK * per;
    if (idx >= total) return;
    int b = idx / per;
    int r = idx - b * per;
    int n = r / Kp;
    int kp = r - n * Kp;
    float w = (kp < c_in) ? Wl[((size_t)b * c_in + kp) * c_out + n]
                          : Wr[((size_t)b * c_in + (kp - c_in)) * c_out + n];
    __nv_bfloat16 hi = __float2bfloat16(w);
    float lo = w - __bfloat162float(hi);
    g_wt_hi[base + idx] = hi;
    g_wt_lo[base + idx] = __float2bfloat16(lo);
}

// ---------------- neighbor-sum gather (msg) ----------------
// c_in == 64: half-warps take even/odd neighbors, combine via shfl.
// c_in >= 128: unroll-by-2 with independent even/odd accumulators (2x MLP).
__global__ void k_gather(const float* __restrict__ x, int in_off, int c_in) {
    int warp = (blockIdx.x * blockDim.x + threadIdx.x) >> 5;
    int lane = threadIdx.x & 31;
    if (warp >= NN) return;
    int start = g_rowptr[warp], end = g_rowptr[warp + 1];
    if (c_in == 64) {
        int c0 = (lane & 15) * 4;
        int par = lane >> 4;   // 0: even neighbors, 1: odd
        float4 a0 = make_float4(0.f, 0.f, 0.f, 0.f);
        for (int j = start + par; j < end; j += 2) {
            int nb = g_col[j];
            const float* row = (in_off < 0) ? (x + (size_t)nb * F_IN)
                                            : (g_hs + (size_t)nb * HS + in_off);
            float4 v = *(const float4*)(row + c0);
            a0.x += v.x; a0.y += v.y; a0.z += v.z; a0.w += v.w;
        }
        a0.x += __shfl_xor_sync(0xFFFFFFFFu, a0.x, 16);
        a0.y += __shfl_xor_sync(0xFFFFFFFFu, a0.y, 16);
        a0.z += __shfl_xor_sync(0xFFFFFFFFu, a0.z, 16);
        a0.w += __shfl_xor_sync(0xFFFFFFFFu, a0.w, 16);
        if (lane < 16) *(float4*)(g_msg + (size_t)warp * 64 + c0) = a0;
        return;
    }
    int c0 = lane * 4;
    int c1 = 128 + lane * 4;
    bool use1 = (c_in > 128);
    float4 e0 = make_float4(0.f, 0.f, 0.f, 0.f);
    float4 e1 = make_float4(0.f, 0.f, 0.f, 0.f);
    float4 o0 = make_float4(0.f, 0.f, 0.f, 0.f);
    float4 o1 = make_float4(0.f, 0.f, 0.f, 0.f);
    int j = start;
    for (; j + 1 < end; j += 2) {
        int nbA = g_col[j];
        int nbB = g_col[j + 1];
        const float* rowA = g_hs + (size_t)nbA * HS + in_off;
        const float* rowB = g_hs + (size_t)nbB * HS + in_off;
        float4 vA = *(const float4*)(rowA + c0);
        float4 vB = *(const float4*)(rowB + c0);
        e0.x += vA.x; e0.y += vA.y; e0.z += vA.z; e0.w += vA.w;
        o0.x += vB.x; o0.y += vB.y; o0.z += vB.z; o0.w += vB.w;
        if (use1) {
            float4 wA = *(const float4*)(rowA + c1);
            float4 wB = *(const float4*)(rowB + c1);
            e1.x += wA.x; e1.y += wA.y; e1.z += wA.z; e1.w += wA.w;
            o1.x += wB.x; o1.y += wB.y; o1.z += wB.z; o1.w += wB.w;
        }
    }
    if (j < end) {
        int nb = g_col[j];
        const float* row = g_hs + (size_t)nb * HS + in_off;
        float4 v = *(const float4*)(row + c0);
        e0.x += v.x; e0.y += v.y; e0.z += v.z; e0.w += v.w;
        if (use1) {
            float4 w = *(const float4*)(row + c1);
            e1.x += w.x; e1.y += w.y; e1.z += w.z; e1.w += w.w;
        }
    }
    e0.x += o0.x; e0.y += o0.y; e0.z += o0.z; e0.w += o0.w;
    e1.x += o1.x; e1.y += o1.y; e1.z += o1.z; e1.w += o1.w;
    float* mrow = g_msg + (size_t)warp * c_in;
    *(float4*)(mrow + c0) = e0;
    if (use1) *(float4*)(mrow + c1) = e1;
}

// ---------------- mma.sync MFConv GEMM (R8 shape + paired-x4 B loads) --------
// 256 threads = 8 warps; tile 128 nodes x 64 cols; warp grid 4(M) x 2(N),
// each warp 32x32 via 2x4 m16n8k16 atoms, 3 passes (AhiBhi, AloBhi, AhiBlo).
// B loaded via 4 paired ldmatrix.x4 per k16 (covers two n8 tiles each).
#define KC 32
#define APAD 40

__global__ void __launch_bounds__(256) k_mfconv_mma(
    const float* __restrict__ x, int in_off, int c_in, int c_out,
    size_t wbase, const float* __restrict__ bl, int out_off,
    const float* __restrict__ Wf, int doff, int do_pool, int do_store)
{
    __shared__ __align__(16) uint16_t sAhi[128 * APAD];
    __shared__ __align__(16) uint16_t sAlo[128 * APAD];
    __shared__ __align__(16) uint16_t sBhi[64 * APAD];
    __shared__ __align__(16) uint16_t sBlo[64 * APAD];
    __shared__ int s_nodes[128];
    __shared__ int s_bb;

    int t = threadIdx.x;
    int lane = t & 31;
    int wid = t >> 5;
    int warp_m = wid & 3;
    int warp_n = wid >> 2;

    int slot0 = blockIdx.y * 128;
    int col0 = blockIdx.x * 64;

    if (t < 128) s_nodes[t] = g_order[slot0 + t];
    if (t == 0) s_bb = g_deg[g_order[slot0]];
    __syncthreads();
    int b = s_bb;

    const int Kp = 2 * c_in;
    const int nch = Kp / KC;
    const size_t wrow0 = wbase + (size_t)b * (size_t)Kp * c_out;

    // fill-thread mapping
    int fa_row = t >> 1;            // A row 0..127
    int fa_kh = (t & 1) * 16;       // k half within chunk
    int fa_node = s_nodes[fa_row];
    const float* fa_msg = (fa_node >= 0) ? (g_msg + (size_t)fa_node * c_in) : nullptr;
    const float* fa_h = nullptr;
    if (fa_node >= 0)
        fa_h = (in_off < 0) ? (x + (size_t)fa_node * F_IN)
                            : (g_hs + (size_t)fa_node * HS + in_off);
    int fb_n = (t & 127) >> 1;      // B row 0..63 (threads 0..127 do B)
    int fb_kh = (t & 1) * 16;
    const __nv_bfloat16* fb_hi = g_wt_hi + wrow0 + (size_t)(col0 + fb_n) * Kp + fb_kh;
    const __nv_bfloat16* fb_lo = g_wt_lo + wrow0 + (size_t)(col0 + fb_n) * Kp + fb_kh;

    uint32_t aHi = smem_u32(sAhi), aLo = smem_u32(sAlo);
    uint32_t bHi = smem_u32(sBhi), bLo = smem_u32(sBlo);

    // per-lane ldmatrix offsets (bytes)
    uint32_t offA[2], offB[2];
#pragma unroll
    for (int mt = 0; mt < 2; mt++) {
        int r = warp_m * 32 + mt * 16 + (lane & 7) + ((lane >> 3) & 1) * 8;
        int kpart = ((lane >> 4) & 1) * 8;
        offA[mt] = (uint32_t)(r * APAD + kpart) * 2u;
    }
#pragma unroll
    for (int np = 0; np < 2; np++) {   // pair of n8 tiles: covers nt=2*np, 2*np+1
        int n = warp_n * 32 + np * 16 + (lane & 7) + ((lane >> 4) & 1) * 8;
        int kpart = ((lane >> 3) & 1) * 8;
        offB[np] = (uint32_t)(n * APAD + kpart) * 2u;
    }

    float acc[2][4][4];
#pragma unroll
    for (int mt = 0; mt < 2; mt++)
#pragma unroll
        for (int nt = 0; nt < 4; nt++)
#pragma unroll
            for (int v = 0; v < 4; v++) acc[mt][nt][v] = 0.f;

    for (int kc = 0; kc < nch; kc++) {
        __syncthreads();
        // ---- fill A (16 fp32 per thread -> hi/lo) ----
        {
            int kglob = kc * KC + fa_kh;
            uint4 hi0, lo0, hi1, lo1;
            if (fa_node >= 0) {
                const float* p = (kglob < c_in) ? (fa_msg + kglob) : (fa_h + kglob - c_in);
                float4 v0 = *(const float4*)(p);
                float4 v1 = *(const float4*)(p + 4);
                float4 v2 = *(const float4*)(p + 8);
                float4 v3 = *(const float4*)(p + 12);
                cvt8(v0, v1, &hi0, &lo0);
                cvt8(v2, v3, &hi1, &lo1);
            } else {
                hi0 = lo0 = hi1 = lo1 = make_uint4(0, 0, 0, 0);
            }
            uint32_t o = (uint32_t)(fa_row * APAD + fa_kh) * 2u;
            *(uint4*)((char*)sAhi + o) = hi0;
            *(uint4*)((char*)sAhi + o + 16) = hi1;
            *(uint4*)((char*)sAlo + o) = lo0;
            *(uint4*)((char*)sAlo + o + 16) = lo1;
        }
        // ---- fill B (threads 0..127) ----
        if (t < 128) {
            const __nv_bfloat16* ph = fb_hi + kc * KC;
            const __nv_bfloat16* pl = fb_lo + kc * KC;
            uint32_t o = (uint32_t)(fb_n * APAD + fb_kh) * 2u;
            *(uint4*)((char*)sBhi + o) = *(const uint4*)(ph);
            *(uint4*)((char*)sBhi + o + 16) = *(const uint4*)(ph + 8);
            *(uint4*)((char*)sBlo + o) = *(const uint4*)(pl);
            *(uint4*)((char*)sBlo + o + 16) = *(const uint4*)(pl + 8);
        }
        __syncthreads();

#pragma unroll
        for (int ks = 0; ks < KC; ks += 16) {
            uint32_t ah[2][4], al[2][4];
            ldm_x4(ah[0], aHi + offA[0] + ks * 2);
            ldm_x4(ah[1], aHi + offA[1] + ks * 2);
            ldm_x4(al[0], aLo + offA[0] + ks * 2);
            ldm_x4(al[1], aLo + offA[1] + ks * 2);
            uint32_t bh[2][4], bl_[2][4];   // [np][4]: regs 0,1 tile 2np; 2,3 tile 2np+1
            ldm_x4(bh[0], bHi + offB[0] + ks * 2);
            ldm_x4(bh[1], bHi + offB[1] + ks * 2);
            ldm_x4(bl_[0], bLo + offB[0] + ks * 2);
            ldm_x4(bl_[1], bLo + offB[1] + ks * 2);
#pragma unroll
            for (int mt = 0; mt < 2; mt++)
#pragma unroll
                for (int nt = 0; nt < 4; nt++) {
                    const uint32_t* bhp = &bh[nt >> 1][(nt & 1) * 2];
                    const uint32_t* blp = &bl_[nt >> 1][(nt & 1) * 2];
                    mma_bf16(acc[mt][nt], ah[mt], bhp);
                    mma_bf16(acc[mt][nt], al[mt], bhp);
                    mma_bf16(acc[mt][nt], ah[mt], blp);
                }
        }
    }

    // ---- epilogue: bias, (optional) store h, fold logit partials ----
    const float* bb = bl + (size_t)b * c_out + col0;
    float pd[2][2][2];   // [mt][row01][class]
    float pp[2][2][2];
#pragma unroll
    for (int mt = 0; mt < 2; mt++)
#pragma unroll
        for (int r = 0; r < 2; r++) {
            pd[mt][r][0] = pd[mt][r][1] = 0.f;
            pp[mt][r][0] = pp[mt][r][1] = 0.f;
        }

#pragma unroll
    for (int mt = 0; mt < 2; mt++) {
        int r0 = warp_m * 32 + mt * 16 + (lane >> 2);
        int r1 = r0 + 8;
        int n0 = s_nodes[r0];
        int n1 = s_nodes[r1];
#pragma unroll
        for (int nt = 0; nt < 4; nt++) {
            int col = warp_n * 32 + nt * 8 + (lane & 3) * 2;
            float2 bv = *(const float2*)(bb + col);
            float o0x = acc[mt][nt][0] + bv.x;
            float o0y = acc[mt][nt][1] + bv.y;
            float o1x = acc[mt][nt][2] + bv.x;
            float o1y = acc[mt][nt][3] + bv.y;
            if (do_store) {
                if (n0 >= 0)
                    *(float2*)(g_hs + (size_t)n0 * HS + out_off + col0 + col) = make_float2(o0x, o0y);
                if (n1 >= 0)
                    *(float2*)(g_hs + (size_t)n1 * HS + out_off + col0 + col) = make_float2(o1x, o1y);
            }
            // logit partials: Wf rows (doff + col0 + col), (.. + 1); 2 classes contiguous
            float4 wf = *(const float4*)(Wf + 2 * (doff + col0 + col));
            pd[mt][0][0] += o0x * wf.x + o0y * wf.z;
            pd[mt][0][1] += o0x * wf.y + o0y * wf.w;
            pd[mt][1][0] += o1x * wf.x + o1y * wf.z;
            pd[mt][1][1] += o1x * wf.y + o1y * wf.w;
            if (do_pool) {
                float4 wp = *(const float4*)(Wf + 2 * (768 + col0 + col));
                pp[mt][0][0] += o0x * wp.x + o0y * wp.z;
                pp[mt][0][1] += o0x * wp.y + o0y * wp.w;
                pp[mt][1][0] += o1x * wp.x + o1y * wp.z;
                pp[mt][1][1] += o1x * wp.y + o1y * wp.w;
            }
        }
    }
    // quad reduce (lanes sharing a row: lane&3 = 0..3)
#pragma unroll
    for (int mt = 0; mt < 2; mt++)
#pragma unroll
        for (int r = 0; r < 2; r++)
#pragma unroll
            for (int c = 0; c < 2; c++) {
                float v = pd[mt][r][c];
                v += __shfl_xor_sync(0xFFFFFFFFu, v, 1);
                v += __shfl_xor_sync(0xFFFFFFFFu, v, 2);
                pd[mt][r][c] = v;
                float w = pp[mt][r][c];
                w += __shfl_xor_sync(0xFFFFFFFFu, w, 1);
                w += __shfl_xor_sync(0xFFFFFFFFu, w, 2);
                pp[mt][r][c] = w;
            }
    if ((lane & 3) == 0) {
        int tile = (doff + col0) / 32 + warp_n;     // direct tile index
        int ptile = col0 / 32 + warp_n;             // pool tile index
#pragma unroll
        for (int mt = 0; mt < 2; mt++) {
            int r0 = warp_m * 32 + mt * 16 + (lane >> 2);
#pragma unroll
            for (int r = 0; r < 2; r++) {
                int node = s_nodes[r0 + r * 8];
                if (node < 0) continue;
                *(float2*)(g_part + ((size_t)node * NDT + tile) * 2) =
                    make_float2(pd[mt][r][0], pd[mt][r][1]);
                if (do_pool)
                    *(float2*)(g_ppart + ((size_t)node * NPT + ptile) * 2) =
                        make_float2(pp[mt][r][0], pp[mt][r][1]);
            }
        }
    }
}

// ---------------- per-graph pool-branch logit sum ----------------
__global__ void k_plsum() {
    __shared__ float S[128];
    int g = blockIdx.x;
    int t = threadIdx.x;
    int comp = t & 15;       // tile*2 + class
    int chunk = t >> 4;      // 0..7
    int s = g_gstart[g], e = g_gstart[g + 1];
    float acc = 0.f;
    for (int i = s + chunk; i < e; i += 8) acc += g_ppart[(size_t)i * 16 + comp];
    S[t] = acc;
    __syncthreads();
    if (t < 64) S[t] += S[t + 64];
    __syncthreads();
    if (t < 32) S[t] += S[t + 32];
    __syncthreads();
    if (t < 16) S[t] += S[t + 16];
    __syncthreads();
    if (t < 2) {
        float v = 0.f;
        for (int k = 0; k < 8; k++) v += S[k * 2 + t];
        g_pl[g * 2 + t] = v;
    }
}

// ---------------- final: sum partials + softmax ----------------
__global__ void k_final(const float* __restrict__ bf, const int* __restrict__ batch,
                        float* __restrict__ out) {
    int i = blockIdx.x * blockDim.x + threadIdx.x;
    if (i >= NN) return;
    float a0 = bf[0], a1 = bf[1];
    const float* pr = g_part + (size_t)i * NDT * 2;
#pragma unroll
    for (int k = 0; k < NDT; k++) {
        float2 v = *(const float2*)(pr + k * 2);
        a0 += v.x; a1 += v.y;
    }
    int g = batch[i];
    a0 += g_pl[g * 2];
    a1 += g_pl[g * 2 + 1];
    float m = fmaxf(a0, a1);
    float e0 = expf(a0 - m), e1 = expf(a1 - m);
    float inv = 1.f / (e0 + e1);
    out[(size_t)i * 2 + 0] = e0 * inv;
    out[(size_t)i * 2 + 1] = e1 * inv;
}

// ---------------- launch ----------------
extern "C" void kernel_launch(void* const* d_in, const int* in_sizes, int n_in,
                              void* d_out, int out_size) {
    const float* x    = (const float*)d_in[0];
    const int*   ei   = (const int*)d_in[1];
    const int*   batch= (const int*)d_in[2];
    const float* Wl[4] = {(const float*)d_in[3], (const float*)d_in[6], (const float*)d_in[9],  (const float*)d_in[12]};
    const float* bl[4] = {(const float*)d_in[4], (const float*)d_in[7], (const float*)d_in[10], (const float*)d_in[13]};
    const float* Wr[4] = {(const float*)d_in[5], (const float*)d_in[8], (const float*)d_in[11], (const float*)d_in[14]};
    const float* Wf = (const float*)d_in[15];
    const float* bf = (const float*)d_in[16];
    float* out = (float*)d_out;

    const int* src = ei;
    const int* dst = ei + NE;

    const int TB = 256;
    const int NB_N = (NN + TB - 1) / TB;
    const int NB_E = (NE + TB - 1) / TB;
    const int NB_S = (SLOT_N + TB - 1) / TB;
    const int NB_W = (NN * 32 + TB - 1) / TB;

    // degree & partition & CSR
    k_init<<<NB_S, TB>>>();
    k_count_deg<<<NB_E, TB>>>(dst);
    k_scan_partial<<<SCAN_NBLK, SCAN_B>>>();
    k_scan_excl_partials<<<1, 512>>>();
    k_scan_write<<<SCAN_NBLK, SCAN_B>>>();
    k_clamp_count<<<NB_N, TB>>>();
    k_pstart<<<1, 32>>>();
    k_scatter_order<<<NB_N, TB>>>();
    k_csr_fill<<<NB_E, TB>>>(src, dst);
    k_csr_sort<<<NB_N, TB>>>();
    k_gstart<<<NB_N, TB>>>(batch);

    // weight prep (transpose + bf16 split)
    const int c_ins  [4] = {64, 128, 128, 256};
    const int c_outs [4] = {128, 128, 256, 256};
    const int in_offs[4] = {-1, 0, 128, 256};
    const int out_offs[4] = {0, 128, 256, 512};
    const size_t wbases[4] = {WOFF0, WOFF1, WOFF2, WOFF3};
    for (int l = 0; l < 4; l++) {
        int total = NBUCK * 2 * c_ins[l] * c_outs[l];
        k_prep_w<<<(total + TB - 1) / TB, TB>>>(Wl[l], Wr[l], c_ins[l], c_outs[l], wbases[l]);
    }

    for (int l = 0; l < 4; l++) {
        k_gather<<<NB_W, TB>>>(x, in_offs[l], c_ins[l]);
        dim3 grid(c_outs[l] / 64, NTILES);
        k_mfconv_mma<<<grid, 256>>>(x, in_offs[l], c_ins[l], c_outs[l],
                                    wbases[l], bl[l], out_offs[l],
                                    Wf, out_offs[l], (l == 3) ? 1 : 0,
                                    (l == 3) ? 0 : 1);
    }

    k_plsum<<<NG, 128>>>();
    k_final<<<NB_N, TB>>>(bf, batch, out);
}

// round 15
// speedup vs baseline: 1.0175x; 1.0175x over previous
#include <cuda_runtime.h>
#include <cuda_bf16.h>
#include <math.h>
#include <stdint.h>

#define NN 200000
#define NE 800000
#define NG 4096
#define F_IN 64
#define HS 768              // concat stride: 128+128+256+256
#define NBUCK 6
#define SLOT_N (NN + NBUCK*128)  // 200768, multiple of 128
#define NTILES (SLOT_N/128)      // 1569
#define SCAN_B 512
#define SCAN_NBLK ((NN + SCAN_B - 1)/SCAN_B)  // 391
#define NDT 24                   // direct logit-partial tiles (768/32)
#define NPT 8                    // pool logit-partial tiles (256/32)

// weight buffer layout: per layer, [bucket][n][k'] with k' = [Wl rows | Wr rows]
#define WOFF0 0
#define WOFF1 (6*128*128)
#define WOFF2 (WOFF1 + 6*256*128)
#define WOFF3 (WOFF2 + 6*256*256)
#define WTOT  (WOFF3 + 6*512*256)

// ---------------- scratch (static device memory; no allocation) ----------------
__device__ float g_hs[(size_t)NN * HS];
__device__ float g_msg[(size_t)NN * 256];
__device__ float g_part[(size_t)NN * NDT * 2];   // per-node direct logit partials
__device__ float g_ppart[(size_t)NN * NPT * 2];  // per-node pool-branch partials
__device__ float g_pl[NG * 2];                   // per-graph pooled logit pair
__device__ __nv_bfloat16 g_wt_hi[WTOT];
__device__ __nv_bfloat16 g_wt_lo[WTOT];
__device__ int   g_rawdeg[NN];
__device__ int   g_deg[NN];
__device__ int   g_rowptr[NN + 1];
__device__ int   g_col[NE];
__device__ int   g_fill[NN];
__device__ int   g_order[SLOT_N];
__device__ int   g_cnt[NBUCK];
__device__ int   g_bfill[NBUCK];
__device__ int   g_pstart[NBUCK + 1];
__device__ int   g_scanpart[SCAN_NBLK];
__device__ int   g_gstart[NG + 1];

// ---------------- helpers ----------------
__device__ __forceinline__ uint32_t smem_u32(const void* p) {
    uint32_t a;
    asm("{ .reg .u64 t; cvta.to.shared.u64 t, %1; cvt.u32.u64 %0, t; }" : "=r"(a) : "l"(p));
    return a;
}
__device__ __forceinline__ void ldm_x4(uint32_t* r, uint32_t addr) {
    asm volatile("ldmatrix.sync.aligned.m8n8.x4.shared.b16 {%0,%1,%2,%3}, [%4];"
                 : "=r"(r[0]), "=r"(r[1]), "=r"(r[2]), "=r"(r[3]) : "r"(addr));
}
__device__ __forceinline__ void ldm_x2(uint32_t* r, uint32_t addr) {
    asm volatile("ldmatrix.sync.aligned.m8n8.x2.shared.b16 {%0,%1}, [%2];"
                 : "=r"(r[0]), "=r"(r[1]) : "r"(addr));
}
__device__ __forceinline__ void mma_bf16(float* d, const uint32_t* a, const uint32_t* b) {
    asm volatile(
        "mma.sync.aligned.m16n8k16.row.col.f32.bf16.bf16.f32 "
        "{%0,%1,%2,%3}, {%4,%5,%6,%7}, {%8,%9}, {%0,%1,%2,%3};"
        : "+f"(d[0]), "+f"(d[1]), "+f"(d[2]), "+f"(d[3])
        : "r"(a[0]), "r"(a[1]), "r"(a[2]), "r"(a[3]), "r"(b[0]), "r"(b[1]));
}
__device__ __forceinline__ uint32_t pk(__nv_bfloat16 a, __nv_bfloat16 b) {
    return (uint32_t)__bfloat16_as_ushort(a) | ((uint32_t)__bfloat16_as_ushort(b) << 16);
}
// convert 8 fp32 -> 8 bf16 hi + 8 bf16 lo (one uint4 each)
__device__ __forceinline__ void cvt8(float4 a, float4 b, uint4* hi, uint4* lo) {
    __nv_bfloat16 h0 = __float2bfloat16(a.x), h1 = __float2bfloat16(a.y);
    __nv_bfloat16 h2 = __float2bfloat16(a.z), h3 = __float2bfloat16(a.w);
    __nv_bfloat16 h4 = __float2bfloat16(b.x), h5 = __float2bfloat16(b.y);
    __nv_bfloat16 h6 = __float2bfloat16(b.z), h7 = __float2bfloat16(b.w);
    hi->x = pk(h0, h1); hi->y = pk(h2, h3); hi->z = pk(h4, h5); hi->w = pk(h6, h7);
    __nv_bfloat16 l0 = __float2bfloat16(a.x - __bfloat162float(h0));
    __nv_bfloat16 l1 = __float2bfloat16(a.y - __bfloat162float(h1));
    __nv_bfloat16 l2 = __float2bfloat16(a.z - __bfloat162float(h2));
    __nv_bfloat16 l3 = __float2bfloat16(a.w - __bfloat162float(h3));
    __nv_bfloat16 l4 = __float2bfloat16(b.x - __bfloat162float(h4));
    __nv_bfloat16 l5 = __float2bfloat16(b.y - __bfloat162float(h5));
    __nv_bfloat16 l6 = __float2bfloat16(b.z - __bfloat162float(h6));
    __nv_bfloat16 l7 = __float2bfloat16(b.w - __bfloat162float(h7));
    lo->x = pk(l0, l1); lo->y = pk(l2, l3); lo->z = pk(l4, l5); lo->w = pk(l6, l7);
}

// ---------------- fused init ----------------
__global__ void k_init() {
    int i = blockIdx.x * blockDim.x + threadIdx.x;
    if (i < NN) g_rawdeg[i] = 0;
    if (i < SLOT_N) g_order[i] = -1;
    if (i < NBUCK) { g_cnt[i] = 0; g_bfill[i] = 0; }
}
__global__ void k_count_deg(const int* __restrict__ dst) {
    int e = blockIdx.x * blockDim.x + threadIdx.x;
    if (e < NE) atomicAdd(&g_rawdeg[dst[e]], 1);
}

// ---------------- scan ----------------
__global__ void k_scan_partial() {
    __shared__ int s[SCAN_B];
    int tid = threadIdx.x;
    int i = blockIdx.x * SCAN_B + tid;
    s[tid] = (i < NN) ? g_rawdeg[i] : 0;
    __syncthreads();
    for (int off = SCAN_B / 2; off > 0; off >>= 1) {
        if (tid < off) s[tid] += s[tid + off];
        __syncthreads();
    }
    if (tid == 0) g_scanpart[blockIdx.x] = s[0];
}
__global__ void k_scan_excl_partials() {   // parallel 512-thread exclusive scan
    __shared__ int s[512];
    int t = threadIdx.x;
    int v = (t < SCAN_NBLK) ? g_scanpart[t] : 0;
    s[t] = v;
    __syncthreads();
    for (int off = 1; off < 512; off <<= 1) {
        int u = (t >= off) ? s[t - off] : 0;
        __syncthreads();
        s[t] += u;
        __syncthreads();
    }
    if (t < SCAN_NBLK) g_scanpart[t] = s[t] - v;
}
__global__ void k_scan_write() {
    __shared__ int s[SCAN_B];
    int tid = threadIdx.x;
    int i = blockIdx.x * SCAN_B + tid;
    int v = (i < NN) ? g_rawdeg[i] : 0;
    s[tid] = v;
    __syncthreads();
    for (int off = 1; off < SCAN_B; off <<= 1) {
        int t = (tid >= off) ? s[tid - off] : 0;
        __syncthreads();
        s[tid] += t;
        __syncthreads();
    }
    int excl = s[tid] - v + g_scanpart[blockIdx.x];
    if (i < NN) g_rowptr[i] = excl;
    if (i == NN - 1) g_rowptr[NN] = excl + v;
}

// ---------------- degree bucket / partition / CSR ----------------
__global__ void k_clamp_count() {
    int i = blockIdx.x * blockDim.x + threadIdx.x;
    if (i >= NN) return;
    int d = g_rawdeg[i]; if (d > 5) d = 5;
    g_deg[i] = d;
    g_fill[i] = 0;
    atomicAdd(&g_cnt[d], 1);
}
__global__ void k_pstart() {
    if (threadIdx.x == 0) {
        int off = 0;
        for (int b = 0; b < NBUCK; b++) { g_pstart[b] = off; off += (g_cnt[b] + 127) & ~127; }
        g_pstart[NBUCK] = off;
    }
}
__global__ void k_scatter_order() {
    int i = blockIdx.x * blockDim.x + threadIdx.x;
    if (i >= NN) return;
    int b = g_deg[i];
    int pos = atomicAdd(&g_bfill[b], 1);
    g_order[g_pstart[b] + pos] = i;
}
__global__ void k_csr_fill(const int* __restrict__ src, const int* __restrict__ dst) {
    int e = blockIdx.x * blockDim.x + threadIdx.x;
    if (e >= NE) return;
    int d = dst[e];
    int pos = atomicAdd(&g_fill[d], 1);
    g_col[g_rowptr[d] + pos] = src[e];
}
__global__ void k_csr_sort() {
    int i = blockIdx.x * blockDim.x + threadIdx.x;
    if (i >= NN) return;
    int a = g_rowptr[i], b = g_rowptr[i + 1];
    for (int j = a + 1; j < b; j++) {
        int v = g_col[j]; int k = j - 1;
        while (k >= a && g_col[k] > v) { g_col[k + 1] = g_col[k]; k--; }
        g_col[k + 1] = v;
    }
}
__global__ void k_gstart(const int* __restrict__ batch) {
    int i = blockIdx.x * blockDim.x + threadIdx.x;
    if (i >= NN) return;
    int b = batch[i];
    int p = (i == 0) ? -1 : batch[i - 1];
    for (int g = p + 1; g <= b; g++) g_gstart[g] = i;
    if (i == NN - 1) { for (int g = b + 1; g <= NG; g++) g_gstart[g] = NN; }
}

// ---------------- weight prep: transpose + bf16 hi/lo split ----------------
__global__ void k_prep_w(const float* __restrict__ Wl, const float* __restrict__ Wr,
                         int c_in, int c_out, size_t base) {
    int idx = blockIdx.x * blockDim.x + threadIdx.x;
    int Kp = 2 * c_in;
    int per = Kp * c_out;
    int total = NBUCK * per;
    if (idx >= total) return;
    int b = idx / per;
    int r = idx - b * per;
    int n = r / Kp;
    int kp = r - n * Kp;
    float w = (kp < c_in) ? Wl[((size_t)b * c_in + kp) * c_out + n]
                          : Wr[((size_t)b * c_in + (kp - c_in)) * c_out + n];
    __nv_bfloat16 hi = __float2bfloat16(w);
    float lo = w - __bfloat162float(hi);
    g_wt_hi[base + idx] = hi;
    g_wt_lo[base + idx] = __float2bfloat16(lo);
}

// ---------------- neighbor-sum gather (msg) ----------------
// c_in == 64 fast path: half-warps take even/odd neighbors, combine via shfl.
__global__ void k_gather(const float* __restrict__ x, int in_off, int c_in) {
    int warp = (blockIdx.x * blockDim.x + threadIdx.x) >> 5;
    int lane = threadIdx.x & 31;
    if (warp >= NN) return;
    int start = g_rowptr[warp], end = g_rowptr[warp + 1];
    if (c_in == 64) {
        int c0 = (lane & 15) * 4;
        int par = lane >> 4;   // 0: even neighbors, 1: odd
        float4 a0 = make_float4(0.f, 0.f, 0.f, 0.f);
        for (int j = start + par; j < end; j += 2) {
            int nb = g_col[j];
            const float* row = (in_off < 0) ? (x + (size_t)nb * F_IN)
                                            : (g_hs + (size_t)nb * HS + in_off);
            float4 v = *(const float4*)(row + c0);
            a0.x += v.x; a0.y += v.y; a0.z += v.z; a0.w += v.w;
        }
        a0.x += __shfl_xor_sync(0xFFFFFFFFu, a0.x, 16);
        a0.y += __shfl_xor_sync(0xFFFFFFFFu, a0.y, 16);
        a0.z += __shfl_xor_sync(0xFFFFFFFFu, a0.z, 16);
        a0.w += __shfl_xor_sync(0xFFFFFFFFu, a0.w, 16);
        if (lane < 16) *(float4*)(g_msg + (size_t)warp * 64 + c0) = a0;
        return;
    }
    int c0 = lane * 4;
    int c1 = 128 + lane * 4;
    float4 a0 = make_float4(0.f, 0.f, 0.f, 0.f);
    float4 a1 = make_float4(0.f, 0.f, 0.f, 0.f);
    bool use1 = (c_in > 128);
    for (int j = start; j < end; j++) {
        int nb = g_col[j];
        const float* row = (in_off < 0) ? (x + (size_t)nb * F_IN)
                                        : (g_hs + (size_t)nb * HS + in_off);
        float4 v = *(const float4*)(row + c0);
        a0.x += v.x; a0.y += v.y; a0.z += v.z; a0.w += v.w;
        if (use1) {
            float4 w = *(const float4*)(row + c1);
            a1.x += w.x; a1.y += w.y; a1.z += w.z; a1.w += w.w;
        }
    }
    float* mrow = g_msg + (size_t)warp * c_in;
    *(float4*)(mrow + c0) = a0;
    if (use1) *(float4*)(mrow + c1) = a1;
}

// ---------------- mma.sync MFConv GEMM (R8/R13 config, verified) ----------------
// 256 threads = 8 warps; tile 128 nodes x 64 cols; warp grid 4(M) x 2(N),
// each warp 32x32 via 2x4 m16n8k16 atoms, 3 passes (AhiBhi, AloBhi, AhiBlo).
// Epilogue folds outputs into per-node logit partials (pool partials on last
// layer); do_store=0 skips the never-read g_hs write for the last layer.
#define KC 32
#define APAD 40

__global__ void __launch_bounds__(256) k_mfconv_mma(
    const float* __restrict__ x, int in_off, int c_in, int c_out,
    size_t wbase, const float* __restrict__ bl, int out_off,
    const float* __restrict__ Wf, int doff, int do_pool, int do_store)
{
    __shared__ __align__(16) uint16_t sAhi[128 * APAD];
    __shared__ __align__(16) uint16_t sAlo[128 * APAD];
    __shared__ __align__(16) uint16_t sBhi[64 * APAD];
    __shared__ __align__(16) uint16_t sBlo[64 * APAD];
    __shared__ int s_nodes[128];
    __shared__ int s_bb;

    int t = threadIdx.x;
    int lane = t & 31;
    int wid = t >> 5;
    int warp_m = wid & 3;
    int warp_n = wid >> 2;

    int slot0 = blockIdx.y * 128;
    int col0 = blockIdx.x * 64;

    if (t < 128) s_nodes[t] = g_order[slot0 + t];
    if (t == 0) s_bb = g_deg[g_order[slot0]];
    __syncthreads();
    int b = s_bb;

    const int Kp = 2 * c_in;
    const int nch = Kp / KC;
    const size_t wrow0 = wbase + (size_t)b * (size_t)Kp * c_out;

    // fill-thread mapping
    int fa_row = t >> 1;            // A row 0..127
    int fa_kh = (t & 1) * 16;       // k half within chunk
    int fa_node = s_nodes[fa_row];
    const float* fa_msg = (fa_node >= 0) ? (g_msg + (size_t)fa_node * c_in) : nullptr;
    const float* fa_h = nullptr;
    if (fa_node >= 0)
        fa_h = (in_off < 0) ? (x + (size_t)fa_node * F_IN)
                            : (g_hs + (size_t)fa_node * HS + in_off);
    int fb_n = (t & 127) >> 1;      // B row 0..63 (threads 0..127 do B)
    int fb_kh = (t & 1) * 16;
    const __nv_bfloat16* fb_hi = g_wt_hi + wrow0 + (size_t)(col0 + fb_n) * Kp + fb_kh;
    const __nv_bfloat16* fb_lo = g_wt_lo + wrow0 + (size_t)(col0 + fb_n) * Kp + fb_kh;

    uint32_t aHi = smem_u32(sAhi), aLo = smem_u32(sAlo);
    uint32_t bHi = smem_u32(sBhi), bLo = smem_u32(sBlo);

    // per-lane ldmatrix offsets (bytes)
    uint32_t offA[2], offB[4];
#pragma unroll
    for (int mt = 0; mt < 2; mt++) {
        int r = warp_m * 32 + mt * 16 + (lane & 7) + ((lane >> 3) & 1) * 8;
        int kpart = ((lane >> 4) & 1) * 8;
        offA[mt] = (uint32_t)(r * APAD + kpart) * 2u;
    }
#pragma unroll
    for (int nt = 0; nt < 4; nt++) {
        int n = warp_n * 32 + nt * 8 + (lane & 7);
        int kpart = (((lane & 15) >> 3) & 1) * 8;
        offB[nt] = (uint32_t)(n * APAD + kpart) * 2u;
    }

    float acc[2][4][4];
#pragma unroll
    for (int mt = 0; mt < 2; mt++)
#pragma unroll
        for (int nt = 0; nt < 4; nt++)
#pragma unroll
            for (int v = 0; v < 4; v++) acc[mt][nt][v] = 0.f;

    for (int kc = 0; kc < nch; kc++) {
        __syncthreads();
        // ---- fill A (16 fp32 per thread -> hi/lo) ----
        {
            int kglob = kc * KC + fa_kh;
            uint4 hi0, lo0, hi1, lo1;
            if (fa_node >= 0) {
                const float* p = (kglob < c_in) ? (fa_msg + kglob) : (fa_h + kglob - c_in);
                float4 v0 = *(const float4*)(p);
                float4 v1 = *(const float4*)(p + 4);
                float4 v2 = *(const float4*)(p + 8);
                float4 v3 = *(const float4*)(p + 12);
                cvt8(v0, v1, &hi0, &lo0);
                cvt8(v2, v3, &hi1, &lo1);
            } else {
                hi0 = lo0 = hi1 = lo1 = make_uint4(0, 0, 0, 0);
            }
            uint32_t o = (uint32_t)(fa_row * APAD + fa_kh) * 2u;
            *(uint4*)((char*)sAhi + o) = hi0;
            *(uint4*)((char*)sAhi + o + 16) = hi1;
            *(uint4*)((char*)sAlo + o) = lo0;
            *(uint4*)((char*)sAlo + o + 16) = lo1;
        }
        // ---- fill B (threads 0..127) ----
        if (t < 128) {
            const __nv_bfloat16* ph = fb_hi + kc * KC;
            const __nv_bfloat16* pl = fb_lo + kc * KC;
            uint32_t o = (uint32_t)(fb_n * APAD + fb_kh) * 2u;
            *(uint4*)((char*)sBhi + o) = *(const uint4*)(ph);
            *(uint4*)((char*)sBhi + o + 16) = *(const uint4*)(ph + 8);
            *(uint4*)((char*)sBlo + o) = *(const uint4*)(pl);
            *(uint4*)((char*)sBlo + o + 16) = *(const uint4*)(pl + 8);
        }
        __syncthreads();

#pragma unroll
        for (int ks = 0; ks < KC; ks += 16) {
            uint32_t ah[2][4], al[2][4];
            ldm_x4(ah[0], aHi + offA[0] + ks * 2);
            ldm_x4(ah[1], aHi + offA[1] + ks * 2);
            ldm_x4(al[0], aLo + offA[0] + ks * 2);
            ldm_x4(al[1], aLo + offA[1] + ks * 2);
            uint32_t bh[4][2], bl_[4][2];
#pragma unroll
            for (int nt = 0; nt < 4; nt++) {
                ldm_x2(bh[nt], bHi + offB[nt] + ks * 2);
                ldm_x2(bl_[nt], bLo + offB[nt] + ks * 2);
            }
#pragma unroll
            for (int mt = 0; mt < 2; mt++)
#pragma unroll
                for (int nt = 0; nt < 4; nt++) {
                    mma_bf16(acc[mt][nt], ah[mt], bh[nt]);
                    mma_bf16(acc[mt][nt], al[mt], bh[nt]);
                    mma_bf16(acc[mt][nt], ah[mt], bl_[nt]);
                }
        }
    }

    // ---- epilogue: bias, (optional) store h, fold logit partials ----
    const float* bb = bl + (size_t)b * c_out + col0;
    float pd[2][2][2];   // [mt][row01][class]
    float pp[2][2][2];
#pragma unroll
    for (int mt = 0; mt < 2; mt++)
#pragma unroll
        for (int r = 0; r < 2; r++) {
            pd[mt][r][0] = pd[mt][r][1] = 0.f;
            pp[mt][r][0] = pp[mt][r][1] = 0.f;
        }

#pragma unroll
    for (int mt = 0; mt < 2; mt++) {
        int r0 = warp_m * 32 + mt * 16 + (lane >> 2);
        int r1 = r0 + 8;
        int n0 = s_nodes[r0];
        int n1 = s_nodes[r1];
#pragma unroll
        for (int nt = 0; nt < 4; nt++) {
            int col = warp_n * 32 + nt * 8 + (lane & 3) * 2;
            float2 bv = *(const float2*)(bb + col);
            float o0x = acc[mt][nt][0] + bv.x;
            float o0y = acc[mt][nt][1] + bv.y;
            float o1x = acc[mt][nt][2] + bv.x;
            float o1y = acc[mt][nt][3] + bv.y;
            if (do_store) {
                if (n0 >= 0)
                    *(float2*)(g_hs + (size_t)n0 * HS + out_off + col0 + col) = make_float2(o0x, o0y);
                if (n1 >= 0)
                    *(float2*)(g_hs + (size_t)n1 * HS + out_off + col0 + col) = make_float2(o1x, o1y);
            }
            // logit partials: Wf rows (doff + col0 + col), (.. + 1); 2 classes contiguous
            float4 wf = *(const float4*)(Wf + 2 * (doff + col0 + col));
            pd[mt][0][0] += o0x * wf.x + o0y * wf.z;
            pd[mt][0][1] += o0x * wf.y + o0y * wf.w;
            pd[mt][1][0] += o1x * wf.x + o1y * wf.z;
            pd[mt][1][1] += o1x * wf.y + o1y * wf.w;
            if (do_pool) {
                float4 wp = *(const float4*)(Wf + 2 * (768 + col0 + col));
                pp[mt][0][0] += o0x * wp.x + o0y * wp.z;
                pp[mt][0][1] += o0x * wp.y + o0y * wp.w;
                pp[mt][1][0] += o1x * wp.x + o1y * wp.z;
                pp[mt][1][1] += o1x * wp.y + o1y * wp.w;
            }
        }
    }
    // quad reduce (lanes sharing a row: lane&3 = 0..3)
#pragma unroll
    for (int mt = 0; mt < 2; mt++)
#pragma unroll
        for (int r = 0; r < 2; r++)
#pragma unroll
            for (int c = 0; c < 2; c++) {
                float v = pd[mt][r][c];
                v += __shfl_xor_sync(0xFFFFFFFFu, v, 1);
                v += __shfl_xor_sync(0xFFFFFFFFu, v, 2);
                pd[mt][r][c] = v;
                float w = pp[mt][r][c];
                w += __shfl_xor_sync(0xFFFFFFFFu, w, 1);
                w += __shfl_xor_sync(0xFFFFFFFFu, w, 2);
                pp[mt][r][c] = w;
            }
    if ((lane & 3) == 0) {
        int tile = (doff + col0) / 32 + warp_n;     // direct tile index
        int ptile = col0 / 32 + warp_n;             // pool tile index
#pragma unroll
        for (int mt = 0; mt < 2; mt++) {
            int r0 = warp_m * 32 + mt * 16 + (lane >> 2);
#pragma unroll
            for (int r = 0; r < 2; r++) {
                int node = s_nodes[r0 + r * 8];
                if (node < 0) continue;
                *(float2*)(g_part + ((size_t)node * NDT + tile) * 2) =
                    make_float2(pd[mt][r][0], pd[mt][r][1]);
                if (do_pool)
                    *(float2*)(g_ppart + ((size_t)node * NPT + ptile) * 2) =
                        make_float2(pp[mt][r][0], pp[mt][r][1]);
            }
        }
    }
}

// ---------------- per-graph pool-branch logit sum ----------------
__global__ void k_plsum() {
    __shared__ float S[128];
    int g = blockIdx.x;
    int t = threadIdx.x;
    int comp = t & 15;       // tile*2 + class
    int chunk = t >> 4;      // 0..7
    int s = g_gstart[g], e = g_gstart[g + 1];
    float acc = 0.f;
    for (int i = s + chunk; i < e; i += 8) acc += g_ppart[(size_t)i * 16 + comp];
    S[t] = acc;
    __syncthreads();
    if (t < 64) S[t] += S[t + 64];
    __syncthreads();
    if (t < 32) S[t] += S[t + 32];
    __syncthreads();
    if (t < 16) S[t] += S[t + 16];
    __syncthreads();
    if (t < 2) {
        float v = 0.f;
        for (int k = 0; k < 8; k++) v += S[k * 2 + t];
        g_pl[g * 2 + t] = v;
    }
}

// ---------------- final: sum partials + softmax ----------------
__global__ void k_final(const float* __restrict__ bf, const int* __restrict__ batch,
                        float* __restrict__ out) {
    int i = blockIdx.x * blockDim.x + threadIdx.x;
    if (i >= NN) return;
    float a0 = bf[0], a1 = bf[1];
    const float* pr = g_part + (size_t)i * NDT * 2;
#pragma unroll
    for (int k = 0; k < NDT; k++) {
        float2 v = *(const float2*)(pr + k * 2);
        a0 += v.x; a1 += v.y;
    }
    int g = batch[i];
    a0 += g_pl[g * 2];
    a1 += g_pl[g * 2 + 1];
    float m = fmaxf(a0, a1);
    float e0 = expf(a0 - m), e1 = expf(a1 - m);
    float inv = 1.f / (e0 + e1);
    out[(size_t)i * 2 + 0] = e0 * inv;
    out[(size_t)i * 2 + 1] = e1 * inv;
}

// ---------------- launch ----------------
extern "C" void kernel_launch(void* const* d_in, const int* in_sizes, int n_in,
                              void* d_out, int out_size) {
    const float* x    = (const float*)d_in[0];
    const int*   ei   = (const int*)d_in[1];
    const int*   batch= (const int*)d_in[2];
    const float* Wl[4] = {(const float*)d_in[3], (const float*)d_in[6], (const float*)d_in[9],  (const float*)d_in[12]};
    const float* bl[4] = {(const float*)d_in[4], (const float*)d_in[7], (const float*)d_in[10], (const float*)d_in[13]};
    const float* Wr[4] = {(const float*)d_in[5], (const float*)d_in[8], (const float*)d_in[11], (const float*)d_in[14]};
    const float* Wf = (const float*)d_in[15];
    const float* bf = (const float*)d_in[16];
    float* out = (float*)d_out;

    const int* src = ei;
    const int* dst = ei + NE;

    const int TB = 256;
    const int NB_N = (NN + TB - 1) / TB;
    const int NB_E = (NE + TB - 1) / TB;
    const int NB_S = (SLOT_N + TB - 1) / TB;
    const int NB_W = (NN * 32 + TB - 1) / TB;

    // degree & partition & CSR
    k_init<<<NB_S, TB>>>();
    k_count_deg<<<NB_E, TB>>>(dst);
    k_scan_partial<<<SCAN_NBLK, SCAN_B>>>();
    k_scan_excl_partials<<<1, 512>>>();
    k_scan_write<<<SCAN_NBLK, SCAN_B>>>();
    k_clamp_count<<<NB_N, TB>>>();
    k_pstart<<<1, 32>>>();
    k_scatter_order<<<NB_N, TB>>>();
    k_csr_fill<<<NB_E, TB>>>(src, dst);
    k_csr_sort<<<NB_N, TB>>>();
    k_gstart<<<NB_N, TB>>>(batch);

    // weight prep (transpose + bf16 split)
    const int c_ins  [4] = {64, 128, 128, 256};
    const int c_outs [4] = {128, 128, 256, 256};
    const int in_offs[4] = {-1, 0, 128, 256};
    const int out_offs[4] = {0, 128, 256, 512};
    const size_t wbases[4] = {WOFF0, WOFF1, WOFF2, WOFF3};
    for (int l = 0; l < 4; l++) {
        int total = NBUCK * 2 * c_ins[l] * c_outs[l];
        k_prep_w<<<(total + TB - 1) / TB, TB>>>(Wl[l], Wr[l], c_ins[l], c_outs[l], wbases[l]);
    }

    for (int l = 0; l < 4; l++) {
        k_gather<<<NB_W, TB>>>(x, in_offs[l], c_ins[l]);
        dim3 grid(c_outs[l] / 64, NTILES);
        k_mfconv_mma<<<grid, 256>>>(x, in_offs[l], c_ins[l], c_outs[l],
                                    wbases[l], bl[l], out_offs[l],
                                    Wf, out_offs[l], (l == 3) ? 1 : 0,
                                    (l == 3) ? 0 : 1);
    }

    k_plsum<<<NG, 128>>>();
    k_final<<<NB_N, TB>>>(bf, batch, out);
}